// round 14
// baseline (speedup 1.0000x reference)
#include <cuda_runtime.h>
#include <cuda_bf16.h>
#include <cstdint>

// Problem constants
#define BN 8
#define CC 64
#define HH 128
#define WW 128
#define NPIX (HH * WW)

// ---------------------------------------------------------------------------
// mma.sync m16n8k16 bf16 (baseline ISA; fragment layout validated R6/R7)
// ---------------------------------------------------------------------------
__device__ __forceinline__ void mma16816(float& d0, float& d1, float& d2, float& d3,
                                         uint32_t a0, uint32_t a1, uint32_t a2, uint32_t a3,
                                         uint32_t b0, uint32_t b1) {
    asm volatile(
        "mma.sync.aligned.m16n8k16.row.col.f32.bf16.bf16.f32 "
        "{%0,%1,%2,%3}, {%4,%5,%6,%7}, {%8,%9}, {%0,%1,%2,%3};"
        : "+f"(d0), "+f"(d1), "+f"(d2), "+f"(d3)
        : "r"(a0), "r"(a1), "r"(a2), "r"(a3), "r"(b0), "r"(b1));
}

// ---------------------------------------------------------------------------
// Scratch
// ---------------------------------------------------------------------------
__device__ float g_x0[BN * CC * NPIX];
__device__ float g_out1[BN * CC * NPIX];
__device__ float g_mean[BN * CC];
__device__ float g_x2[BN * CC];
// out2 in pre-converted aux layout: [b][h][p][stage(4)][16 hi][16 lo] bf16
__device__ __nv_bfloat16 g_o2aux[BN * HH * 128 * 128];
// Permuted dense-conv weights, hi/lo interleaved:
// uint4[(kstep36)*8*32 + n*32 + lane] = (bh0, bh1, bl0, bl1)
#define BPW_U32 (36 * 8 * 32 * 4)
__device__ uint32_t g_bpA[BPW_U32];   // w0
__device__ uint32_t g_bpF[BPW_U32];   // wf
// Permuted W3 fragments, hi/lo interleaved
#define BP3_U32 (9 * 2 * 4 * 4 * 32 * 4)
__device__ uint32_t g_bp3[BP3_U32];

// ---------------------------------------------------------------------------
// Dense-conv weight permutation: 36 ksteps (stage*9 + tap), 16 ch per stage
// ---------------------------------------------------------------------------
__global__ __launch_bounds__(256) void wconv_prep(const float* __restrict__ w,
                                                  uint32_t* __restrict__ bp)
{
    int idx = blockIdx.x * 256 + threadIdx.x;
    if (idx >= BPW_U32) return;
    int word  = idx & 3;
    int lane  = (idx >> 2) & 31;
    int nt    = (idx >> 7) & 7;
    int kstep = idx >> 10;
    int stage = kstep / 9;
    int tap   = kstep - stage * 9;
    int split = word >> 1;
    int reg   = word & 1;

    int tg = lane & 3;
    int g  = lane >> 2;
    int ic = stage * 16 + 2 * tg + (reg ? 8 : 0);
    int oc = nt * 8 + g;

    float v0 = w[(oc * CC + ic) * 9 + tap];
    float v1 = w[(oc * CC + ic + 1) * 9 + tap];
    __nv_bfloat16 h0 = __float2bfloat16(v0);
    __nv_bfloat16 h1 = __float2bfloat16(v1);
    __nv_bfloat16 e0, e1;
    if (split == 0) { e0 = h0; e1 = h1; }
    else {
        e0 = __float2bfloat16(v0 - __bfloat162float(h0));
        e1 = __float2bfloat16(v1 - __bfloat162float(h1));
    }
    __nv_bfloat162 p(e0, e1);
    bp[idx] = *(uint32_t*)&p;
}

// ---------------------------------------------------------------------------
// W3 fragment permutation (hi/lo interleaved in uint4)
// ---------------------------------------------------------------------------
__global__ __launch_bounds__(256) void w3_prep_frag(const float* __restrict__ w3,
                                                    uint32_t* __restrict__ bp)
{
    int idx = blockIdx.x * 256 + threadIdx.x;
    if (idx >= BP3_U32) return;
    int word = idx & 3;
    int lane = (idx >> 2) & 31;
    int t = idx >> 7;
    int ks = t & 3;  t >>= 2;
    int nt = t & 3;  t >>= 2;
    int hf = t & 1;  t >>= 1;
    int k  = t;
    int split = word >> 1;
    int r     = word & 1;

    int g  = lane >> 2;
    int tg = lane & 3;
    int cout = hf * 32 + nt * 8 + g;
    const float* row = w3 + (long)(cout * 9 + k) * 64;

    int kk = 16 * ks + 2 * tg + (r ? 8 : 0);
    float v0 = row[kk];
    float v1 = row[kk + 1];
    __nv_bfloat16 h0 = __float2bfloat16(v0);
    __nv_bfloat16 h1 = __float2bfloat16(v1);
    __nv_bfloat16 e0, e1;
    if (split == 0) { e0 = h0; e1 = h1; }
    else {
        e0 = __float2bfloat16(v0 - __bfloat162float(h0));
        e1 = __float2bfloat16(v1 - __bfloat162float(h1));
    }
    __nv_bfloat162 p(e0, e1);
    bp[idx] = *(uint32_t*)&p;
}

// ---------------------------------------------------------------------------
// Dense 3x3 conv via mma.sync bf16 hi/lo implicit GEMM.
//   4 K-stages of 16 channels; CPAD=40, 31.2KB smem, 4 CTAs/SM (~100KB L1
//   so B weights are L1-resident).
//   2D warp tiling: 8 warps = 4 m-groups x 2 n-groups; per warp 2 m-tiles x
//   4 n-tiles -> B LDG.128 halved (4/kstep), smaller B reg footprint lets
//   ptxas pipeline the next kstep's loads under the MMAs.
// ---------------------------------------------------------------------------
#define CPAD 40
#define CONV_SMEM (390 * CPAD * 2)     // 31200 B

__global__ __launch_bounds__(256, 4) void conv3x3_wmma(
    const float* __restrict__ in, const __nv_bfloat16* __restrict__ aux,
    const uint32_t* __restrict__ bp,
    const float* __restrict__ bias, const float* __restrict__ res,
    float* __restrict__ outp, int add_res)
{
    extern __shared__ __align__(16) char smem[];
    __nv_bfloat16* S = (__nv_bfloat16*)smem;   // [e(390)][CPAD]: hi 0-15, lo 16-31

    const int tid  = threadIdx.x;
    const int warp = tid >> 5;
    const int lane = tid & 31;
    const int g    = lane >> 2;
    const int tg   = lane & 3;
    const int wm   = warp & 3;      // m-group: pixels 32*wm ..
    const int wn   = warp >> 2;     // n-group: ocs 32*wn ..
    const int h = blockIdx.x;
    const int b = blockIdx.y;

    // hoisted halo coordinates (elements e = dy*130 + j)
    const int e0 = tid, e1 = tid + 256;
    int gh0 = h - 1 + e0 / 130, gw0 = e0 % 130 - 1;
    int gh1 = h - 1 + e1 / 130, gw1 = e1 % 130 - 1;
    const bool a0v = (unsigned)gh0 < (unsigned)HH && (unsigned)gw0 < (unsigned)WW;
    const bool a1v = (e1 < 390) && (unsigned)gh1 < (unsigned)HH && (unsigned)gw1 < (unsigned)WW;
    const long go0 = (long)gh0 * WW + gw0;
    const long go1 = (long)gh1 * WW + gw1;
    // aux row offsets (bf16 units)
    const __nv_bfloat16* axbase = aux + (long)b * HH * 128 * 128;
    const long ao0 = ((long)gh0 * 128 + gw0) * 128;
    const long ao1 = ((long)gh1 * 128 + gw1) * 128;

    float d[2][4][4];
#pragma unroll
    for (int mt = 0; mt < 2; mt++)
#pragma unroll
        for (int n = 0; n < 4; n++)
#pragma unroll
            for (int r = 0; r < 4; r++) d[mt][n][r] = 0.f;

    for (int stage = 0; stage < 4; stage++) {
        if (stage) __syncthreads();   // previous stage reads done

        if (aux) {
            // ---- fast staging: copy 64B (16 hi + 16 lo bf16) per element --
            const uint4 zz = make_uint4(0u, 0u, 0u, 0u);
            const uint4* s0 = (const uint4*)(axbase + ao0 + stage * 32);
            uint4* d0p = (uint4*)&S[e0 * CPAD];
#pragma unroll
            for (int q = 0; q < 4; q++) d0p[q] = a0v ? s0[q] : zz;
            if (e1 < 390) {
                const uint4* s1 = (const uint4*)(axbase + ao1 + stage * 32);
                uint4* d1p = (uint4*)&S[e1 * CPAD];
#pragma unroll
                for (int q = 0; q < 4; q++) d1p[q] = a1v ? s1[q] : zz;
            }
        } else {
            // ---- inline conversion staging (conv0 path) -------------------
            const float* pl = in + (long)(b * CC + stage * 16) * NPIX;
#pragma unroll 4
            for (int c2 = 0; c2 < 8; c2++) {
                float f00 = a0v ? pl[go0] : 0.f;
                float f10 = a0v ? pl[NPIX + go0] : 0.f;
                __nv_bfloat16 h00 = __float2bfloat16(f00);
                __nv_bfloat16 h10 = __float2bfloat16(f10);
                __nv_bfloat16 l00 = __float2bfloat16(f00 - __bfloat162float(h00));
                __nv_bfloat16 l10 = __float2bfloat16(f10 - __bfloat162float(h10));
                __nv_bfloat162 ph0(h00, h10), pl0(l00, l10);
                *(uint32_t*)&S[e0 * CPAD + 2 * c2]      = *(uint32_t*)&ph0;
                *(uint32_t*)&S[e0 * CPAD + 16 + 2 * c2] = *(uint32_t*)&pl0;
                if (e1 < 390) {
                    float f01 = a1v ? pl[go1] : 0.f;
                    float f11 = a1v ? pl[NPIX + go1] : 0.f;
                    __nv_bfloat16 h01 = __float2bfloat16(f01);
                    __nv_bfloat16 h11 = __float2bfloat16(f11);
                    __nv_bfloat16 l01 = __float2bfloat16(f01 - __bfloat162float(h01));
                    __nv_bfloat16 l11 = __float2bfloat16(f11 - __bfloat162float(h11));
                    __nv_bfloat162 ph1(h01, h11), pl1(l01, l11);
                    *(uint32_t*)&S[e1 * CPAD + 2 * c2]      = *(uint32_t*)&ph1;
                    *(uint32_t*)&S[e1 * CPAD + 16 + 2 * c2] = *(uint32_t*)&pl1;
                }
                pl += 2 * NPIX;
            }
        }
        __syncthreads();

        // ---- 9 taps of this stage's K=16 GEMM -----------------------------
#pragma unroll 3
        for (int tap = 0; tap < 9; tap++) {
            const int ky = tap / 3, kx = tap - 3 * ky;

            // A fragments for 2 m-tiles
            uint32_t ah[2][4], al[2][4];
#pragma unroll
            for (int mt = 0; mt < 2; mt++) {
                const __nv_bfloat16* ab =
                    S + (ky * 130 + 32 * wm + 16 * mt + g + kx) * CPAD + 2 * tg;
                ah[mt][0] = *(const uint32_t*)ab;
                ah[mt][1] = *(const uint32_t*)(ab + 8 * CPAD);
                ah[mt][2] = *(const uint32_t*)(ab + 8);
                ah[mt][3] = *(const uint32_t*)(ab + 8 * CPAD + 8);
                al[mt][0] = *(const uint32_t*)(ab + 16);
                al[mt][1] = *(const uint32_t*)(ab + 8 * CPAD + 16);
                al[mt][2] = *(const uint32_t*)(ab + 24);
                al[mt][3] = *(const uint32_t*)(ab + 8 * CPAD + 24);
            }

            const uint4* br = (const uint4*)bp + (size_t)(stage * 9 + tap) * 256
                              + (wn * 4) * 32 + lane;
#pragma unroll
            for (int n = 0; n < 4; n++) {
                uint4 bq = br[n * 32];   // (bh0, bh1, bl0, bl1)
#pragma unroll
                for (int mt = 0; mt < 2; mt++) {
                    mma16816(d[mt][n][0], d[mt][n][1], d[mt][n][2], d[mt][n][3],
                             ah[mt][0], ah[mt][1], ah[mt][2], ah[mt][3], bq.x, bq.y);
                    mma16816(d[mt][n][0], d[mt][n][1], d[mt][n][2], d[mt][n][3],
                             ah[mt][0], ah[mt][1], ah[mt][2], ah[mt][3], bq.z, bq.w);
                    mma16816(d[mt][n][0], d[mt][n][1], d[mt][n][2], d[mt][n][3],
                             al[mt][0], al[mt][1], al[mt][2], al[mt][3], bq.x, bq.y);
                }
            }
        }
    }

#pragma unroll
    for (int mt = 0; mt < 2; mt++) {
        const int p0 = 32 * wm + 16 * mt + g;
        const int p1 = p0 + 8;
#pragma unroll
        for (int n = 0; n < 4; n++) {
            const int oc = 32 * wn + n * 8 + 2 * tg;
            const float b0v = bias[oc];
            const float b1v = bias[oc + 1];
            long base0 = ((long)(b * CC + oc) * HH + h) * WW;
            long base1 = base0 + (long)HH * WW;
            float v00 = d[mt][n][0] + b0v;
            float v01 = d[mt][n][1] + b1v;
            float v10 = d[mt][n][2] + b0v;
            float v11 = d[mt][n][3] + b1v;
            if (add_res) {
                v00 += res[base0 + p0]; v01 += res[base1 + p0];
                v10 += res[base0 + p1]; v11 += res[base1 + p1];
            }
            outp[base0 + p0] = v00;
            outp[base1 + p0] = v01;
            outp[base0 + p1] = v10;
            outp[base1 + p1] = v11;
        }
    }
}

// ---------------------------------------------------------------------------
// mean / eca / dw (unchanged)
// ---------------------------------------------------------------------------
__global__ __launch_bounds__(256) void mean_kernel(const float* __restrict__ x0,
                                                   float* __restrict__ mean)
{
    const int bc = blockIdx.x;
    const float4* p4 = (const float4*)(x0 + (long)bc * NPIX);
    float s = 0.f;
    for (int i = threadIdx.x; i < NPIX / 4; i += 256) {
        float4 v = p4[i];
        s += v.x + v.y + v.z + v.w;
    }
    __shared__ float red[256];
    red[threadIdx.x] = s;
    __syncthreads();
    for (int off = 128; off > 0; off >>= 1) {
        if (threadIdx.x < off) red[threadIdx.x] += red[threadIdx.x + off];
        __syncthreads();
    }
    if (threadIdx.x == 0) mean[bc] = red[0] * (1.f / (float)NPIX);
}

__global__ void eca_kernel(const float* __restrict__ mean,
                           const float* __restrict__ w2,
                           const float* __restrict__ b2,
                           float* __restrict__ x2o)
{
    const int t = threadIdx.x;
    const int b = t >> 6, c = t & 63;
    float m0 = (c > 0)  ? mean[b * CC + c - 1] : 0.f;
    float m1 =            mean[b * CC + c];
    float m2 = (c < 63) ? mean[b * CC + c + 1] : 0.f;
    x2o[t] = w2[0] * m0 + w2[1] * m1 + w2[2] * m2 + b2[0];
}

__global__ __launch_bounds__(256) void dw_kernel(
    const float* __restrict__ x0, const float* __restrict__ w1,
    const float* __restrict__ b1, const float* __restrict__ x2,
    float* __restrict__ outp)
{
    __shared__ float t[10][130];
    const int h0 = blockIdx.x * 8;
    const int c  = blockIdx.y;
    const int b  = blockIdx.z;
    const float* src = x0 + (long)(b * CC + c) * NPIX;

    for (int i = threadIdx.x; i < 10 * 130; i += 256) {
        int r = i / 130, col = i % 130;
        int gh = h0 - 1 + r, gw = col - 1;
        float v = 0.f;
        if ((unsigned)gh < (unsigned)HH && (unsigned)gw < (unsigned)WW)
            v = src[gh * WW + gw];
        t[r][col] = v;
    }
    float wk[9];
#pragma unroll
    for (int k = 0; k < 9; k++) wk[k] = w1[c * 9 + k];
    const float bb = b1[c] + x2[b * CC + c];
    __syncthreads();

    float* dst = outp + (long)(b * CC + c) * NPIX + (long)h0 * WW;
    for (int p = threadIdx.x; p < 8 * WW; p += 256) {
        int r = p / WW, wc = p % WW;
        float a = bb;
#pragma unroll
        for (int dy = 0; dy < 3; dy++)
#pragma unroll
            for (int dx = 0; dx < 3; dx++)
                a += wk[dy * 3 + dx] * t[r + dy][wc + dx];
        dst[p] = a;
    }
}

// ---------------------------------------------------------------------------
// Dynamic conv via per-tap GEMMs; epilogue writes out2 directly in the
// pre-converted aux layout [b][h][p][stage][16 hi][16 lo] bf16.
// ---------------------------------------------------------------------------
#define APITCH 72
#define DOFF_B3  50688
#define DYN_SMEM (50688 + 2304)

__global__ __launch_bounds__(256, 3) void dynconv_tap(
    const float* __restrict__ out1, const float* __restrict__ x0,
    const uint32_t* __restrict__ bp3, const float* __restrict__ b3,
    __nv_bfloat16* __restrict__ o2aux)
{
    extern __shared__ __align__(16) char smem[];
    __nv_bfloat16* Ahi = (__nv_bfloat16*)smem;           // [0, 18432)
    __nv_bfloat16* Alo = Ahi + 128 * APITCH;             // [18432, 36864)
    float* x0s = (float*)smem;                           // aliases A region
    float* b3s = (float*)(smem + DOFF_B3);

    const int tid  = threadIdx.x;
    const int warp = tid >> 5;
    const int lane = tid & 31;
    const int g    = lane >> 2;
    const int tg   = lane & 3;
    const int m0   = warp * 16;
    const int hrow = blockIdx.x;
    const int b = blockIdx.y;

    // ---- stage A: out1[b,:,h,:] -> [p][c] bf16 hi/lo -----------------------
    {
        const long base = (long)b * CC * NPIX + (long)hrow * WW;
        for (int i = tid; i < 128 * 32; i += 256) {
            int p  = i >> 5;
            int cp = i & 31;
            float v0 = out1[base + (long)(2 * cp)     * NPIX + p];
            float v1 = out1[base + (long)(2 * cp + 1) * NPIX + p];
            __nv_bfloat16 h0 = __float2bfloat16(v0);
            __nv_bfloat16 h1 = __float2bfloat16(v1);
            __nv_bfloat16 l0 = __float2bfloat16(v0 - __bfloat162float(h0));
            __nv_bfloat16 l1 = __float2bfloat16(v1 - __bfloat162float(h1));
            __nv_bfloat162 ph(h0, h1), plp(l0, l1);
            *(uint32_t*)&Ahi[p * APITCH + 2 * cp] = *(uint32_t*)&ph;
            *(uint32_t*)&Alo[p * APITCH + 2 * cp] = *(uint32_t*)&plp;
        }
        for (int i = tid; i < 576; i += 256) b3s[i] = b3[i];
    }
    __syncthreads();

    // ---- A fragments in registers -----------------------------------------
    uint32_t Ah[4][4], Al[4][4];
#pragma unroll
    for (int k = 0; k < 4; k++) {
        int col = k * 16 + tg * 2;
        Ah[k][0] = *(const uint32_t*)&Ahi[(m0 + g)     * APITCH + col];
        Ah[k][1] = *(const uint32_t*)&Ahi[(m0 + g + 8) * APITCH + col];
        Ah[k][2] = *(const uint32_t*)&Ahi[(m0 + g)     * APITCH + col + 8];
        Ah[k][3] = *(const uint32_t*)&Ahi[(m0 + g + 8) * APITCH + col + 8];
        Al[k][0] = *(const uint32_t*)&Alo[(m0 + g)     * APITCH + col];
        Al[k][1] = *(const uint32_t*)&Alo[(m0 + g + 8) * APITCH + col];
        Al[k][2] = *(const uint32_t*)&Alo[(m0 + g)     * APITCH + col + 8];
        Al[k][3] = *(const uint32_t*)&Alo[(m0 + g + 8) * APITCH + col + 8];
    }

    const int p0 = m0 + g;
    const int p1 = p0 + 8;
    __nv_bfloat16* arow = o2aux + ((long)(b * HH + hrow)) * 128 * 128;

    for (int hf = 0; hf < 2; hf++) {
        const int cbase = hf * 32;
        __syncthreads();   // fragments loaded / previous half done with x0s
        // ---- stage x0 halo for this half: [3][32][132] (overwrites A) -----
        for (int i = tid; i < 3 * 32 * 132; i += 256) {
            int dy = i / (32 * 132);
            int r  = i - dy * (32 * 132);
            int c  = r / 132;
            int j  = r - c * 132;
            int gh = hrow - 1 + dy, gw = j - 1;
            float v = 0.f;
            if ((unsigned)gh < (unsigned)HH && (unsigned)gw < (unsigned)WW)
                v = x0[((long)(b * CC + cbase + c) * HH + gh) * WW + gw];
            x0s[i] = v;
        }
        __syncthreads();

        float acc[4][4];
#pragma unroll
        for (int n = 0; n < 4; n++)
#pragma unroll
            for (int r = 0; r < 4; r++) acc[n][r] = 0.f;

#pragma unroll
        for (int k = 0; k < 9; k++) {
            const int dy = k / 3, dx = k - 3 * dy;
            const uint4* Bq = (const uint4*)bp3 + (size_t)(k * 2 + hf) * 512 + lane;
#pragma unroll
            for (int n = 0; n < 4; n++) {
                float d0 = 0.f, d1 = 0.f, d2 = 0.f, d3 = 0.f;
#pragma unroll
                for (int ks = 0; ks < 4; ks++) {
                    uint4 bq = Bq[(n * 4 + ks) * 32];   // (bh0, bh1, bl0, bl1)
                    mma16816(d0, d1, d2, d3, Ah[ks][0], Ah[ks][1], Ah[ks][2], Ah[ks][3], bq.x, bq.y);
                    mma16816(d0, d1, d2, d3, Ah[ks][0], Ah[ks][1], Ah[ks][2], Ah[ks][3], bq.z, bq.w);
                    mma16816(d0, d1, d2, d3, Al[ks][0], Al[ks][1], Al[ks][2], Al[ks][3], bq.x, bq.y);
                }
                const int cl = n * 8 + 2 * tg;
                const float bb0 = b3s[(cbase + cl) * 9 + k];
                const float bb1 = b3s[(cbase + cl + 1) * 9 + k];
                const float* xr0 = &x0s[(dy * 32 + cl) * 132];
                const float* xr1 = xr0 + 132;
                acc[n][0] += (d0 + bb0) * xr0[p0 + dx];
                acc[n][1] += (d1 + bb1) * xr1[p0 + dx];
                acc[n][2] += (d2 + bb0) * xr0[p1 + dx];
                acc[n][3] += (d3 + bb1) * xr1[p1 + dx];
            }
        }

        // ---- leaky + aux store (hi/lo bf16, layout [p][s][16hi][16lo]) -----
#pragma unroll
        for (int n = 0; n < 4; n++) {
            const int c = cbase + n * 8 + 2 * tg;   // even channel
            const int s = c >> 4;
            const int ci = c & 15;
            float v00 = acc[n][0], v01 = acc[n][1], v10 = acc[n][2], v11 = acc[n][3];
            v00 = (v00 >= 0.f) ? v00 : 0.2f * v00;
            v01 = (v01 >= 0.f) ? v01 : 0.2f * v01;
            v10 = (v10 >= 0.f) ? v10 : 0.2f * v10;
            v11 = (v11 >= 0.f) ? v11 : 0.2f * v11;
            __nv_bfloat16 h00 = __float2bfloat16(v00);
            __nv_bfloat16 h01 = __float2bfloat16(v01);
            __nv_bfloat16 l00 = __float2bfloat16(v00 - __bfloat162float(h00));
            __nv_bfloat16 l01 = __float2bfloat16(v01 - __bfloat162float(h01));
            __nv_bfloat16 h10 = __float2bfloat16(v10);
            __nv_bfloat16 h11 = __float2bfloat16(v11);
            __nv_bfloat16 l10 = __float2bfloat16(v10 - __bfloat162float(h10));
            __nv_bfloat16 l11 = __float2bfloat16(v11 - __bfloat162float(h11));
            __nv_bfloat16* r0 = arow + (long)p0 * 128 + s * 32 + ci;
            __nv_bfloat16* r1 = arow + (long)p1 * 128 + s * 32 + ci;
            __nv_bfloat162 ph0(h00, h01), pl0(l00, l01);
            __nv_bfloat162 ph1(h10, h11), pl1(l10, l11);
            *(uint32_t*)r0        = *(uint32_t*)&ph0;
            *(uint32_t*)(r0 + 16) = *(uint32_t*)&pl0;
            *(uint32_t*)r1        = *(uint32_t*)&ph1;
            *(uint32_t*)(r1 + 16) = *(uint32_t*)&pl1;
        }
    }
}

// ---------------------------------------------------------------------------
// Launch
// ---------------------------------------------------------------------------
extern "C" void kernel_launch(void* const* d_in, const int* in_sizes, int n_in,
                              void* d_out, int out_size)
{
    const float* x  = (const float*)d_in[0];
    const float* w0 = (const float*)d_in[1];
    const float* b0 = (const float*)d_in[2];
    const float* w1 = (const float*)d_in[3];
    const float* b1 = (const float*)d_in[4];
    const float* w2 = (const float*)d_in[5];
    const float* b2 = (const float*)d_in[6];
    const float* w3 = (const float*)d_in[7];
    const float* b3 = (const float*)d_in[8];
    const float* wf = (const float*)d_in[9];
    const float* bf = (const float*)d_in[10];
    float* out = (float*)d_out;

    float *px0, *pout1, *pmean, *px2;
    __nv_bfloat16 *po2aux;
    uint32_t *pbpA, *pbpF, *pbp3;
    cudaGetSymbolAddress((void**)&px0,    g_x0);
    cudaGetSymbolAddress((void**)&pout1,  g_out1);
    cudaGetSymbolAddress((void**)&pmean,  g_mean);
    cudaGetSymbolAddress((void**)&px2,    g_x2);
    cudaGetSymbolAddress((void**)&po2aux, g_o2aux);
    cudaGetSymbolAddress((void**)&pbpA,   g_bpA);
    cudaGetSymbolAddress((void**)&pbpF,   g_bpF);
    cudaGetSymbolAddress((void**)&pbp3,   g_bp3);

    cudaFuncSetAttribute(conv3x3_wmma,
                         cudaFuncAttributeMaxDynamicSharedMemorySize, CONV_SMEM);
    cudaFuncSetAttribute(dynconv_tap,
                         cudaFuncAttributeMaxDynamicSharedMemorySize, DYN_SMEM);

    // 0) weight permutations
    wconv_prep<<<(BPW_U32 + 255) / 256, 256>>>(w0, pbpA);
    wconv_prep<<<(BPW_U32 + 255) / 256, 256>>>(wf, pbpF);
    w3_prep_frag<<<(BP3_U32 + 255) / 256, 256>>>(w3, pbp3);
    // 1) conv0 on tensor cores (inline conversion path)
    conv3x3_wmma<<<dim3(HH, BN), 256, CONV_SMEM>>>(x, nullptr, pbpA, b0, nullptr, px0, 0);
    // 2) per-channel spatial mean
    mean_kernel<<<BN * CC, 256>>>(px0, pmean);
    // 3) ECA conv1d over channel axis
    eca_kernel<<<1, BN * CC>>>(pmean, w2, b2, px2);
    // 4) depthwise + channel attention
    dw_kernel<<<dim3(HH / 8, CC, BN), 256>>>(px0, w1, b1, px2, pout1);
    // 5) dynamic conv: per-tap GEMMs; writes out2 in aux bf16 hi/lo layout
    dynconv_tap<<<dim3(HH, BN), 256, DYN_SMEM>>>(pout1, px0, pbp3, b3, po2aux);
    // 6) final conv on tensor cores (fast aux staging) + residual
    conv3x3_wmma<<<dim3(HH, BN), 256, CONV_SMEM>>>(nullptr, po2aux, pbpF, bf, x, out, 1);
}

// round 16
// speedup vs baseline: 1.0194x; 1.0194x over previous
#include <cuda_runtime.h>
#include <cuda_bf16.h>
#include <cstdint>

// Problem constants
#define BN 8
#define CC 64
#define HH 128
#define WW 128
#define NPIX (HH * WW)

// ---------------------------------------------------------------------------
// mma.sync m16n8k16 bf16 (baseline ISA; fragment layout validated R6/R7)
// ---------------------------------------------------------------------------
__device__ __forceinline__ void mma16816(float& d0, float& d1, float& d2, float& d3,
                                         uint32_t a0, uint32_t a1, uint32_t a2, uint32_t a3,
                                         uint32_t b0, uint32_t b1) {
    asm volatile(
        "mma.sync.aligned.m16n8k16.row.col.f32.bf16.bf16.f32 "
        "{%0,%1,%2,%3}, {%4,%5,%6,%7}, {%8,%9}, {%0,%1,%2,%3};"
        : "+f"(d0), "+f"(d1), "+f"(d2), "+f"(d3)
        : "r"(a0), "r"(a1), "r"(a2), "r"(a3), "r"(b0), "r"(b1));
}

// ---------------------------------------------------------------------------
// Scratch
// ---------------------------------------------------------------------------
__device__ float g_x0[BN * CC * NPIX];
__device__ float g_out2[BN * CC * NPIX];
__device__ float g_mean[BN * CC];
__device__ float g_x2[BN * CC];
// out1 in A-staging layout: [b][h][p][64 hi bf16][64 lo bf16]
__device__ __nv_bfloat16 g_o1aux[BN * HH * 128 * 128];
// Permuted dense-conv weights, hi/lo interleaved:
// uint4[(kstep36)*8*32 + n*32 + lane] = (bh0, bh1, bl0, bl1)
#define BPW_U32 (36 * 8 * 32 * 4)
__device__ uint32_t g_bpA[BPW_U32];   // w0
__device__ uint32_t g_bpF[BPW_U32];   // wf
// Permuted W3 fragments, hi/lo interleaved
#define BP3_U32 (9 * 2 * 4 * 4 * 32 * 4)
__device__ uint32_t g_bp3[BP3_U32];

// ---------------------------------------------------------------------------
// Dense-conv weight permutation: 36 ksteps (stage*9 + tap), 16 ch per stage
// ---------------------------------------------------------------------------
__global__ __launch_bounds__(256) void wconv_prep(const float* __restrict__ w,
                                                  uint32_t* __restrict__ bp)
{
    int idx = blockIdx.x * 256 + threadIdx.x;
    if (idx >= BPW_U32) return;
    int word  = idx & 3;
    int lane  = (idx >> 2) & 31;
    int nt    = (idx >> 7) & 7;
    int kstep = idx >> 10;
    int stage = kstep / 9;
    int tap   = kstep - stage * 9;
    int split = word >> 1;
    int reg   = word & 1;

    int tg = lane & 3;
    int g  = lane >> 2;
    int ic = stage * 16 + 2 * tg + (reg ? 8 : 0);
    int oc = nt * 8 + g;

    float v0 = w[(oc * CC + ic) * 9 + tap];
    float v1 = w[(oc * CC + ic + 1) * 9 + tap];
    __nv_bfloat16 hh0 = __float2bfloat16(v0);
    __nv_bfloat16 hh1 = __float2bfloat16(v1);
    __nv_bfloat16 e0, e1;
    if (split == 0) { e0 = hh0; e1 = hh1; }
    else {
        e0 = __float2bfloat16(v0 - __bfloat162float(hh0));
        e1 = __float2bfloat16(v1 - __bfloat162float(hh1));
    }
    __nv_bfloat162 p(e0, e1);
    bp[idx] = *(uint32_t*)&p;
}

// ---------------------------------------------------------------------------
// W3 fragment permutation (hi/lo interleaved in uint4)
// ---------------------------------------------------------------------------
__global__ __launch_bounds__(256) void w3_prep_frag(const float* __restrict__ w3,
                                                    uint32_t* __restrict__ bp)
{
    int idx = blockIdx.x * 256 + threadIdx.x;
    if (idx >= BP3_U32) return;
    int word = idx & 3;
    int lane = (idx >> 2) & 31;
    int t = idx >> 7;
    int ks = t & 3;  t >>= 2;
    int nt = t & 3;  t >>= 2;
    int hf = t & 1;  t >>= 1;
    int k  = t;
    int split = word >> 1;
    int r     = word & 1;

    int g  = lane >> 2;
    int tg = lane & 3;
    int cout = hf * 32 + nt * 8 + g;
    const float* row = w3 + (long)(cout * 9 + k) * 64;

    int kk = 16 * ks + 2 * tg + (r ? 8 : 0);
    float v0 = row[kk];
    float v1 = row[kk + 1];
    __nv_bfloat16 hh0 = __float2bfloat16(v0);
    __nv_bfloat16 hh1 = __float2bfloat16(v1);
    __nv_bfloat16 e0, e1;
    if (split == 0) { e0 = hh0; e1 = hh1; }
    else {
        e0 = __float2bfloat16(v0 - __bfloat162float(hh0));
        e1 = __float2bfloat16(v1 - __bfloat162float(hh1));
    }
    __nv_bfloat162 p(e0, e1);
    bp[idx] = *(uint32_t*)&p;
}

// ---------------------------------------------------------------------------
// Dense 3x3 conv via mma.sync bf16 hi/lo implicit GEMM (R12 best config).
//   4 K-stages of 16 channels; CPAD=40, 31.2KB smem, 4 CTAs/SM; 1x8 tiling.
// ---------------------------------------------------------------------------
#define CPAD 40
#define CONV_SMEM (390 * CPAD * 2)     // 31200 B

__global__ __launch_bounds__(256, 4) void conv3x3_wmma(
    const float* __restrict__ in, const uint32_t* __restrict__ bp,
    const float* __restrict__ bias, const float* __restrict__ res,
    float* __restrict__ outp, int add_res)
{
    extern __shared__ __align__(16) char smem[];
    __nv_bfloat16* S = (__nv_bfloat16*)smem;   // [e(390)][CPAD]: hi 0-15, lo 16-31

    const int tid  = threadIdx.x;
    const int warp = tid >> 5;
    const int lane = tid & 31;
    const int g    = lane >> 2;
    const int tg   = lane & 3;
    const int m0   = warp * 16;
    const int h = blockIdx.x;
    const int b = blockIdx.y;

    const int e0 = tid, e1 = tid + 256;
    int gh0 = h - 1 + e0 / 130, gw0 = e0 % 130 - 1;
    int gh1 = h - 1 + e1 / 130, gw1 = e1 % 130 - 1;
    const bool a0v = (unsigned)gh0 < (unsigned)HH && (unsigned)gw0 < (unsigned)WW;
    const bool a1v = (e1 < 390) && (unsigned)gh1 < (unsigned)HH && (unsigned)gw1 < (unsigned)WW;
    const long go0 = (long)gh0 * WW + gw0;
    const long go1 = (long)gh1 * WW + gw1;

    float d[8][4];
#pragma unroll
    for (int n = 0; n < 8; n++)
#pragma unroll
        for (int r = 0; r < 4; r++) d[n][r] = 0.f;

    for (int stage = 0; stage < 4; stage++) {
        if (stage) __syncthreads();

        const float* pl = in + (long)(b * CC + stage * 16) * NPIX;
#pragma unroll 4
        for (int c2 = 0; c2 < 8; c2++) {
            float f00 = a0v ? pl[go0] : 0.f;
            float f10 = a0v ? pl[NPIX + go0] : 0.f;
            __nv_bfloat16 h00 = __float2bfloat16(f00);
            __nv_bfloat16 h10 = __float2bfloat16(f10);
            __nv_bfloat16 l00 = __float2bfloat16(f00 - __bfloat162float(h00));
            __nv_bfloat16 l10 = __float2bfloat16(f10 - __bfloat162float(h10));
            __nv_bfloat162 ph0(h00, h10), pl0(l00, l10);
            *(uint32_t*)&S[e0 * CPAD + 2 * c2]      = *(uint32_t*)&ph0;
            *(uint32_t*)&S[e0 * CPAD + 16 + 2 * c2] = *(uint32_t*)&pl0;
            if (e1 < 390) {
                float f01 = a1v ? pl[go1] : 0.f;
                float f11 = a1v ? pl[NPIX + go1] : 0.f;
                __nv_bfloat16 h01 = __float2bfloat16(f01);
                __nv_bfloat16 h11 = __float2bfloat16(f11);
                __nv_bfloat16 l01 = __float2bfloat16(f01 - __bfloat162float(h01));
                __nv_bfloat16 l11 = __float2bfloat16(f11 - __bfloat162float(h11));
                __nv_bfloat162 ph1(h01, h11), pl1(l01, l11);
                *(uint32_t*)&S[e1 * CPAD + 2 * c2]      = *(uint32_t*)&ph1;
                *(uint32_t*)&S[e1 * CPAD + 16 + 2 * c2] = *(uint32_t*)&pl1;
            }
            pl += 2 * NPIX;
        }
        __syncthreads();

#pragma unroll 3
        for (int tap = 0; tap < 9; tap++) {
            const int ky = tap / 3, kx = tap - 3 * ky;
            const __nv_bfloat16* ab = S + (ky * 130 + m0 + g + kx) * CPAD + 2 * tg;
            uint32_t ah0 = *(const uint32_t*)ab;
            uint32_t ah1 = *(const uint32_t*)(ab + 8 * CPAD);
            uint32_t ah2 = *(const uint32_t*)(ab + 8);
            uint32_t ah3 = *(const uint32_t*)(ab + 8 * CPAD + 8);
            uint32_t al0 = *(const uint32_t*)(ab + 16);
            uint32_t al1 = *(const uint32_t*)(ab + 8 * CPAD + 16);
            uint32_t al2 = *(const uint32_t*)(ab + 24);
            uint32_t al3 = *(const uint32_t*)(ab + 8 * CPAD + 24);
            const uint4* br = (const uint4*)bp + (size_t)(stage * 9 + tap) * 256 + lane;
#pragma unroll
            for (int n = 0; n < 8; n++) {
                uint4 bq = br[n * 32];
                mma16816(d[n][0], d[n][1], d[n][2], d[n][3],
                         ah0, ah1, ah2, ah3, bq.x, bq.y);
                mma16816(d[n][0], d[n][1], d[n][2], d[n][3],
                         ah0, ah1, ah2, ah3, bq.z, bq.w);
                mma16816(d[n][0], d[n][1], d[n][2], d[n][3],
                         al0, al1, al2, al3, bq.x, bq.y);
            }
        }
    }

    const int p0 = m0 + g;
    const int p1 = p0 + 8;
#pragma unroll
    for (int n = 0; n < 8; n++) {
        const int oc = n * 8 + 2 * tg;
        const float b0v = bias[oc];
        const float b1v = bias[oc + 1];
        long base0 = ((long)(b * CC + oc) * HH + h) * WW;
        long base1 = base0 + (long)HH * WW;
        float v00 = d[n][0] + b0v;
        float v01 = d[n][1] + b1v;
        float v10 = d[n][2] + b0v;
        float v11 = d[n][3] + b1v;
        if (add_res) {
            v00 += res[base0 + p0]; v01 += res[base1 + p0];
            v10 += res[base0 + p1]; v11 += res[base1 + p1];
        }
        outp[base0 + p0] = v00;
        outp[base1 + p0] = v01;
        outp[base0 + p1] = v10;
        outp[base1 + p1] = v11;
    }
}

// ---------------------------------------------------------------------------
// mean / eca (unchanged)
// ---------------------------------------------------------------------------
__global__ __launch_bounds__(256) void mean_kernel(const float* __restrict__ x0,
                                                   float* __restrict__ mean)
{
    const int bc = blockIdx.x;
    const float4* p4 = (const float4*)(x0 + (long)bc * NPIX);
    float s = 0.f;
    for (int i = threadIdx.x; i < NPIX / 4; i += 256) {
        float4 v = p4[i];
        s += v.x + v.y + v.z + v.w;
    }
    __shared__ float red[256];
    red[threadIdx.x] = s;
    __syncthreads();
    for (int off = 128; off > 0; off >>= 1) {
        if (threadIdx.x < off) red[threadIdx.x] += red[threadIdx.x + off];
        __syncthreads();
    }
    if (threadIdx.x == 0) mean[bc] = red[0] * (1.f / (float)NPIX);
}

__global__ void eca_kernel(const float* __restrict__ mean,
                           const float* __restrict__ w2,
                           const float* __restrict__ b2,
                           float* __restrict__ x2o)
{
    const int t = threadIdx.x;
    const int b = t >> 6, c = t & 63;
    float m0 = (c > 0)  ? mean[b * CC + c - 1] : 0.f;
    float m1 =            mean[b * CC + c];
    float m2 = (c < 63) ? mean[b * CC + c + 1] : 0.f;
    x2o[t] = w2[0] * m0 + w2[1] * m1 + w2[2] * m2 + b2[0];
}

// ---------------------------------------------------------------------------
// Depthwise 3x3 + channel attention, 2 channels per CTA, writing out1
// directly in dynconv's A-staging layout: [b][h][p][64 hi][64 lo] bf16.
// ---------------------------------------------------------------------------
__global__ __launch_bounds__(256) void dw_kernel2(
    const float* __restrict__ x0, const float* __restrict__ w1,
    const float* __restrict__ b1, const float* __restrict__ x2,
    __nv_bfloat16* __restrict__ o1aux)
{
    __shared__ float t[2][10][130];
    const int h0 = blockIdx.x * 8;
    const int cp = blockIdx.y;          // channel pair 0..31
    const int b  = blockIdx.z;
    const int c0 = 2 * cp;

    for (int i = threadIdx.x; i < 2 * 10 * 130; i += 256) {
        int ch = i / 1300;
        int r2 = i - ch * 1300;
        int r = r2 / 130, col = r2 - r * 130;
        int gh = h0 - 1 + r, gw = col - 1;
        float v = 0.f;
        if ((unsigned)gh < (unsigned)HH && (unsigned)gw < (unsigned)WW)
            v = x0[((long)(b * CC + c0 + ch) * HH + gh) * WW + gw];
        t[ch][r][col] = v;
    }
    float wk0[9], wk1[9];
#pragma unroll
    for (int k = 0; k < 9; k++) { wk0[k] = w1[c0 * 9 + k]; wk1[k] = w1[(c0 + 1) * 9 + k]; }
    const float bb0 = b1[c0] + x2[b * CC + c0];
    const float bb1 = b1[c0 + 1] + x2[b * CC + c0 + 1];
    __syncthreads();

    for (int p = threadIdx.x; p < 8 * WW; p += 256) {
        int r = p >> 7, wc = p & 127;
        float a0 = bb0, a1 = bb1;
#pragma unroll
        for (int dy = 0; dy < 3; dy++)
#pragma unroll
            for (int dx = 0; dx < 3; dx++) {
                a0 += wk0[dy * 3 + dx] * t[0][r + dy][wc + dx];
                a1 += wk1[dy * 3 + dx] * t[1][r + dy][wc + dx];
            }
        __nv_bfloat16 bh0 = __float2bfloat16(a0);
        __nv_bfloat16 bh1 = __float2bfloat16(a1);
        __nv_bfloat16 bl0 = __float2bfloat16(a0 - __bfloat162float(bh0));
        __nv_bfloat16 bl1 = __float2bfloat16(a1 - __bfloat162float(bh1));
        __nv_bfloat16* dst = o1aux + ((long)((b * HH + h0 + r) * 128 + wc)) * 128 + 2 * cp;
        __nv_bfloat162 ph(bh0, bh1), plq(bl0, bl1);
        *(uint32_t*)dst        = *(uint32_t*)&ph;
        *(uint32_t*)(dst + 64) = *(uint32_t*)&plq;
    }
}

// ---------------------------------------------------------------------------
// Dynamic conv via per-tap GEMMs (R12 structure); A staged via coalesced
// uint4 copy from o1aux (producer pre-converted); out2 fp32.
// ---------------------------------------------------------------------------
#define APITCH 72
#define DOFF_B3  50688
#define DYN_SMEM (50688 + 2304)

__global__ __launch_bounds__(256, 3) void dynconv_tap(
    const __nv_bfloat16* __restrict__ o1aux, const float* __restrict__ x0,
    const uint32_t* __restrict__ bp3, const float* __restrict__ b3,
    float* __restrict__ out2)
{
    extern __shared__ __align__(16) char smem[];
    __nv_bfloat16* Ahi = (__nv_bfloat16*)smem;           // [0, 18432)
    __nv_bfloat16* Alo = Ahi + 128 * APITCH;             // [18432, 36864)
    float* x0s = (float*)smem;                           // aliases A region
    float* b3s = (float*)(smem + DOFF_B3);

    const int tid  = threadIdx.x;
    const int warp = tid >> 5;
    const int lane = tid & 31;
    const int g    = lane >> 2;
    const int tg   = lane & 3;
    const int m0   = warp * 16;
    const int hrow = blockIdx.x;
    const int b = blockIdx.y;

    // ---- stage A: coalesced uint4 copy from o1aux --------------------------
    {
        const __nv_bfloat16* arow = o1aux + ((long)(b * HH + hrow)) * 128 * 128;
        for (int i = tid; i < 2048; i += 256) {
            int p  = i >> 4;
            int ch = i & 15;            // 0..7 hi chunks, 8..15 lo chunks
            uint4 v = *(const uint4*)(arow + (long)p * 128 + ch * 8);
            __nv_bfloat16* dstbase = (ch < 8) ? Ahi : Alo;
            *(uint4*)&dstbase[p * APITCH + (ch & 7) * 8] = v;
        }
        for (int i = tid; i < 576; i += 256) b3s[i] = b3[i];
    }
    __syncthreads();

    // ---- A fragments in registers -----------------------------------------
    uint32_t Ah[4][4], Al[4][4];
#pragma unroll
    for (int k = 0; k < 4; k++) {
        int col = k * 16 + tg * 2;
        Ah[k][0] = *(const uint32_t*)&Ahi[(m0 + g)     * APITCH + col];
        Ah[k][1] = *(const uint32_t*)&Ahi[(m0 + g + 8) * APITCH + col];
        Ah[k][2] = *(const uint32_t*)&Ahi[(m0 + g)     * APITCH + col + 8];
        Ah[k][3] = *(const uint32_t*)&Ahi[(m0 + g + 8) * APITCH + col + 8];
        Al[k][0] = *(const uint32_t*)&Alo[(m0 + g)     * APITCH + col];
        Al[k][1] = *(const uint32_t*)&Alo[(m0 + g + 8) * APITCH + col];
        Al[k][2] = *(const uint32_t*)&Alo[(m0 + g)     * APITCH + col + 8];
        Al[k][3] = *(const uint32_t*)&Alo[(m0 + g + 8) * APITCH + col + 8];
    }

    const int p0 = m0 + g;
    const int p1 = p0 + 8;

    for (int hf = 0; hf < 2; hf++) {
        const int cbase = hf * 32;
        __syncthreads();   // fragments loaded / previous half done with x0s
        for (int i = tid; i < 3 * 32 * 132; i += 256) {
            int dy = i / (32 * 132);
            int r  = i - dy * (32 * 132);
            int c  = r / 132;
            int j  = r - c * 132;
            int gh = hrow - 1 + dy, gw = j - 1;
            float v = 0.f;
            if ((unsigned)gh < (unsigned)HH && (unsigned)gw < (unsigned)WW)
                v = x0[((long)(b * CC + cbase + c) * HH + gh) * WW + gw];
            x0s[i] = v;
        }
        __syncthreads();

        float acc[4][4];
#pragma unroll
        for (int n = 0; n < 4; n++)
#pragma unroll
            for (int r = 0; r < 4; r++) acc[n][r] = 0.f;

#pragma unroll
        for (int k = 0; k < 9; k++) {
            const int dy = k / 3, dx = k - 3 * dy;
            const uint4* Bq = (const uint4*)bp3 + (size_t)(k * 2 + hf) * 512 + lane;
#pragma unroll
            for (int n = 0; n < 4; n++) {
                float d0 = 0.f, d1 = 0.f, d2 = 0.f, d3 = 0.f;
#pragma unroll
                for (int ks = 0; ks < 4; ks++) {
                    uint4 bq = Bq[(n * 4 + ks) * 32];
                    mma16816(d0, d1, d2, d3, Ah[ks][0], Ah[ks][1], Ah[ks][2], Ah[ks][3], bq.x, bq.y);
                    mma16816(d0, d1, d2, d3, Ah[ks][0], Ah[ks][1], Ah[ks][2], Ah[ks][3], bq.z, bq.w);
                    mma16816(d0, d1, d2, d3, Al[ks][0], Al[ks][1], Al[ks][2], Al[ks][3], bq.x, bq.y);
                }
                const int cl = n * 8 + 2 * tg;
                const float bb0 = b3s[(cbase + cl) * 9 + k];
                const float bb1 = b3s[(cbase + cl + 1) * 9 + k];
                const float* xr0 = &x0s[(dy * 32 + cl) * 132];
                const float* xr1 = xr0 + 132;
                acc[n][0] += (d0 + bb0) * xr0[p0 + dx];
                acc[n][1] += (d1 + bb1) * xr1[p0 + dx];
                acc[n][2] += (d2 + bb0) * xr0[p1 + dx];
                acc[n][3] += (d3 + bb1) * xr1[p1 + dx];
            }
        }

#pragma unroll
        for (int n = 0; n < 4; n++) {
            const int c = cbase + n * 8 + 2 * tg;
            long base0 = ((long)(b * CC + c) * HH + hrow) * WW;
            long base1 = base0 + (long)HH * WW;
            float v00 = acc[n][0], v01 = acc[n][1], v10 = acc[n][2], v11 = acc[n][3];
            v00 = (v00 >= 0.f) ? v00 : 0.2f * v00;
            v01 = (v01 >= 0.f) ? v01 : 0.2f * v01;
            v10 = (v10 >= 0.f) ? v10 : 0.2f * v10;
            v11 = (v11 >= 0.f) ? v11 : 0.2f * v11;
            out2[base0 + p0] = v00;
            out2[base1 + p0] = v01;
            out2[base0 + p1] = v10;
            out2[base1 + p1] = v11;
        }
    }
}

// ---------------------------------------------------------------------------
// Launch
// ---------------------------------------------------------------------------
extern "C" void kernel_launch(void* const* d_in, const int* in_sizes, int n_in,
                              void* d_out, int out_size)
{
    const float* x  = (const float*)d_in[0];
    const float* w0 = (const float*)d_in[1];
    const float* b0 = (const float*)d_in[2];
    const float* w1 = (const float*)d_in[3];
    const float* b1 = (const float*)d_in[4];
    const float* w2 = (const float*)d_in[5];
    const float* b2 = (const float*)d_in[6];
    const float* w3 = (const float*)d_in[7];
    const float* b3 = (const float*)d_in[8];
    const float* wf = (const float*)d_in[9];
    const float* bf = (const float*)d_in[10];
    float* out = (float*)d_out;

    float *px0, *pout2, *pmean, *px2;
    __nv_bfloat16 *po1aux;
    uint32_t *pbpA, *pbpF, *pbp3;
    cudaGetSymbolAddress((void**)&px0,    g_x0);
    cudaGetSymbolAddress((void**)&pout2,  g_out2);
    cudaGetSymbolAddress((void**)&pmean,  g_mean);
    cudaGetSymbolAddress((void**)&px2,    g_x2);
    cudaGetSymbolAddress((void**)&po1aux, g_o1aux);
    cudaGetSymbolAddress((void**)&pbpA,   g_bpA);
    cudaGetSymbolAddress((void**)&pbpF,   g_bpF);
    cudaGetSymbolAddress((void**)&pbp3,   g_bp3);

    cudaFuncSetAttribute(conv3x3_wmma,
                         cudaFuncAttributeMaxDynamicSharedMemorySize, CONV_SMEM);
    cudaFuncSetAttribute(dynconv_tap,
                         cudaFuncAttributeMaxDynamicSharedMemorySize, DYN_SMEM);

    // 0) weight permutations
    wconv_prep<<<(BPW_U32 + 255) / 256, 256>>>(w0, pbpA);
    wconv_prep<<<(BPW_U32 + 255) / 256, 256>>>(wf, pbpF);
    w3_prep_frag<<<(BP3_U32 + 255) / 256, 256>>>(w3, pbp3);
    // 1) conv0 on tensor cores
    conv3x3_wmma<<<dim3(HH, BN), 256, CONV_SMEM>>>(x, pbpA, b0, nullptr, px0, 0);
    // 2) per-channel spatial mean
    mean_kernel<<<BN * CC, 256>>>(px0, pmean);
    // 3) ECA conv1d over channel axis
    eca_kernel<<<1, BN * CC>>>(pmean, w2, b2, px2);
    // 4) depthwise + channel attention -> out1 in A-staging bf16 layout
    dw_kernel2<<<dim3(HH / 8, CC / 2, BN), 256>>>(px0, w1, b1, px2, po1aux);
    // 5) dynamic conv: per-tap GEMMs, coalesced A staging, register-fused apply
    dynconv_tap<<<dim3(HH, BN), 256, DYN_SMEM>>>(po1aux, px0, pbp3, b3, pout2);
    // 6) final conv on tensor cores + residual
    conv3x3_wmma<<<dim3(HH, BN), 256, CONV_SMEM>>>(pout2, pbpF, bf, x, out, 1);
}

// round 17
// speedup vs baseline: 1.0776x; 1.0571x over previous
#include <cuda_runtime.h>
#include <cuda_bf16.h>
#include <cstdint>

// Problem constants
#define BN 8
#define CC 64
#define HH 128
#define WW 128
#define NPIX (HH * WW)

// ---------------------------------------------------------------------------
// mma.sync m16n8k16 bf16 (baseline ISA; fragment layout validated R6/R7)
// ---------------------------------------------------------------------------
__device__ __forceinline__ void mma16816(float& d0, float& d1, float& d2, float& d3,
                                         uint32_t a0, uint32_t a1, uint32_t a2, uint32_t a3,
                                         uint32_t b0, uint32_t b1) {
    asm volatile(
        "mma.sync.aligned.m16n8k16.row.col.f32.bf16.bf16.f32 "
        "{%0,%1,%2,%3}, {%4,%5,%6,%7}, {%8,%9}, {%0,%1,%2,%3};"
        : "+f"(d0), "+f"(d1), "+f"(d2), "+f"(d3)
        : "r"(a0), "r"(a1), "r"(a2), "r"(a3), "r"(b0), "r"(b1));
}

// ---------------------------------------------------------------------------
// Scratch
// ---------------------------------------------------------------------------
__device__ float g_x0[BN * CC * NPIX];
__device__ float g_out1[BN * CC * NPIX];
__device__ float g_out2[BN * CC * NPIX];
__device__ float g_mean[BN * CC];
__device__ float g_x2[BN * CC];
// Permuted dense-conv weights, hi/lo interleaved:
// uint4[(kstep36)*8*32 + n*32 + lane] = (bh0, bh1, bl0, bl1)
#define BPW_U32 (36 * 8 * 32 * 4)
__device__ uint32_t g_bpA[BPW_U32];   // w0
__device__ uint32_t g_bpF[BPW_U32];   // wf
// Permuted W3 fragments, hi/lo interleaved
#define BP3_U32 (9 * 2 * 4 * 4 * 32 * 4)
__device__ uint32_t g_bp3[BP3_U32];

// ---------------------------------------------------------------------------
// Dense-conv weight permutation: 36 ksteps (stage*9 + tap), 16 ch per stage
// ---------------------------------------------------------------------------
__global__ __launch_bounds__(256) void wconv_prep(const float* __restrict__ w,
                                                  uint32_t* __restrict__ bp)
{
    int idx = blockIdx.x * 256 + threadIdx.x;
    if (idx >= BPW_U32) return;
    int word  = idx & 3;
    int lane  = (idx >> 2) & 31;
    int nt    = (idx >> 7) & 7;
    int kstep = idx >> 10;
    int stage = kstep / 9;
    int tap   = kstep - stage * 9;
    int split = word >> 1;
    int reg   = word & 1;

    int tg = lane & 3;
    int g  = lane >> 2;
    int ic = stage * 16 + 2 * tg + (reg ? 8 : 0);
    int oc = nt * 8 + g;

    float v0 = w[(oc * CC + ic) * 9 + tap];
    float v1 = w[(oc * CC + ic + 1) * 9 + tap];
    __nv_bfloat16 hh0 = __float2bfloat16(v0);
    __nv_bfloat16 hh1 = __float2bfloat16(v1);
    __nv_bfloat16 e0, e1;
    if (split == 0) { e0 = hh0; e1 = hh1; }
    else {
        e0 = __float2bfloat16(v0 - __bfloat162float(hh0));
        e1 = __float2bfloat16(v1 - __bfloat162float(hh1));
    }
    __nv_bfloat162 p(e0, e1);
    bp[idx] = *(uint32_t*)&p;
}

// ---------------------------------------------------------------------------
// W3 fragment permutation (hi/lo interleaved in uint4)
// ---------------------------------------------------------------------------
__global__ __launch_bounds__(256) void w3_prep_frag(const float* __restrict__ w3,
                                                    uint32_t* __restrict__ bp)
{
    int idx = blockIdx.x * 256 + threadIdx.x;
    if (idx >= BP3_U32) return;
    int word = idx & 3;
    int lane = (idx >> 2) & 31;
    int t = idx >> 7;
    int ks = t & 3;  t >>= 2;
    int nt = t & 3;  t >>= 2;
    int hf = t & 1;  t >>= 1;
    int k  = t;
    int split = word >> 1;
    int r     = word & 1;

    int g  = lane >> 2;
    int tg = lane & 3;
    int cout = hf * 32 + nt * 8 + g;
    const float* row = w3 + (long)(cout * 9 + k) * 64;

    int kk = 16 * ks + 2 * tg + (r ? 8 : 0);
    float v0 = row[kk];
    float v1 = row[kk + 1];
    __nv_bfloat16 hh0 = __float2bfloat16(v0);
    __nv_bfloat16 hh1 = __float2bfloat16(v1);
    __nv_bfloat16 e0, e1;
    if (split == 0) { e0 = hh0; e1 = hh1; }
    else {
        e0 = __float2bfloat16(v0 - __bfloat162float(hh0));
        e1 = __float2bfloat16(v1 - __bfloat162float(hh1));
    }
    __nv_bfloat162 p(e0, e1);
    bp[idx] = *(uint32_t*)&p;
}

// ---------------------------------------------------------------------------
// Dense 3x3 conv via mma.sync bf16 hi/lo implicit GEMM (R12 best config).
//   4 K-stages of 16 channels; CPAD=40, 31.2KB smem, 4 CTAs/SM; 1x8 tiling.
// ---------------------------------------------------------------------------
#define CPAD 40
#define CONV_SMEM (390 * CPAD * 2)     // 31200 B

__global__ __launch_bounds__(256, 4) void conv3x3_wmma(
    const float* __restrict__ in, const uint32_t* __restrict__ bp,
    const float* __restrict__ bias, const float* __restrict__ res,
    float* __restrict__ outp, int add_res)
{
    extern __shared__ __align__(16) char smem[];
    __nv_bfloat16* S = (__nv_bfloat16*)smem;   // [e(390)][CPAD]: hi 0-15, lo 16-31

    const int tid  = threadIdx.x;
    const int warp = tid >> 5;
    const int lane = tid & 31;
    const int g    = lane >> 2;
    const int tg   = lane & 3;
    const int m0   = warp * 16;
    const int h = blockIdx.x;
    const int b = blockIdx.y;

    const int e0 = tid, e1 = tid + 256;
    int gh0 = h - 1 + e0 / 130, gw0 = e0 % 130 - 1;
    int gh1 = h - 1 + e1 / 130, gw1 = e1 % 130 - 1;
    const bool a0v = (unsigned)gh0 < (unsigned)HH && (unsigned)gw0 < (unsigned)WW;
    const bool a1v = (e1 < 390) && (unsigned)gh1 < (unsigned)HH && (unsigned)gw1 < (unsigned)WW;
    const long go0 = (long)gh0 * WW + gw0;
    const long go1 = (long)gh1 * WW + gw1;

    float d[8][4];
#pragma unroll
    for (int n = 0; n < 8; n++)
#pragma unroll
        for (int r = 0; r < 4; r++) d[n][r] = 0.f;

    for (int stage = 0; stage < 4; stage++) {
        if (stage) __syncthreads();

        const float* pl = in + (long)(b * CC + stage * 16) * NPIX;
#pragma unroll 4
        for (int c2 = 0; c2 < 8; c2++) {
            float f00 = a0v ? pl[go0] : 0.f;
            float f10 = a0v ? pl[NPIX + go0] : 0.f;
            __nv_bfloat16 h00 = __float2bfloat16(f00);
            __nv_bfloat16 h10 = __float2bfloat16(f10);
            __nv_bfloat16 l00 = __float2bfloat16(f00 - __bfloat162float(h00));
            __nv_bfloat16 l10 = __float2bfloat16(f10 - __bfloat162float(h10));
            __nv_bfloat162 ph0(h00, h10), pl0(l00, l10);
            *(uint32_t*)&S[e0 * CPAD + 2 * c2]      = *(uint32_t*)&ph0;
            *(uint32_t*)&S[e0 * CPAD + 16 + 2 * c2] = *(uint32_t*)&pl0;
            if (e1 < 390) {
                float f01 = a1v ? pl[go1] : 0.f;
                float f11 = a1v ? pl[NPIX + go1] : 0.f;
                __nv_bfloat16 h01 = __float2bfloat16(f01);
                __nv_bfloat16 h11 = __float2bfloat16(f11);
                __nv_bfloat16 l01 = __float2bfloat16(f01 - __bfloat162float(h01));
                __nv_bfloat16 l11 = __float2bfloat16(f11 - __bfloat162float(h11));
                __nv_bfloat162 ph1(h01, h11), pl1(l01, l11);
                *(uint32_t*)&S[e1 * CPAD + 2 * c2]      = *(uint32_t*)&ph1;
                *(uint32_t*)&S[e1 * CPAD + 16 + 2 * c2] = *(uint32_t*)&pl1;
            }
            pl += 2 * NPIX;
        }
        __syncthreads();

#pragma unroll 3
        for (int tap = 0; tap < 9; tap++) {
            const int ky = tap / 3, kx = tap - 3 * ky;
            const __nv_bfloat16* ab = S + (ky * 130 + m0 + g + kx) * CPAD + 2 * tg;
            uint32_t ah0 = *(const uint32_t*)ab;
            uint32_t ah1 = *(const uint32_t*)(ab + 8 * CPAD);
            uint32_t ah2 = *(const uint32_t*)(ab + 8);
            uint32_t ah3 = *(const uint32_t*)(ab + 8 * CPAD + 8);
            uint32_t al0 = *(const uint32_t*)(ab + 16);
            uint32_t al1 = *(const uint32_t*)(ab + 8 * CPAD + 16);
            uint32_t al2 = *(const uint32_t*)(ab + 24);
            uint32_t al3 = *(const uint32_t*)(ab + 8 * CPAD + 24);
            const uint4* br = (const uint4*)bp + (size_t)(stage * 9 + tap) * 256 + lane;
#pragma unroll
            for (int n = 0; n < 8; n++) {
                uint4 bq = br[n * 32];
                mma16816(d[n][0], d[n][1], d[n][2], d[n][3],
                         ah0, ah1, ah2, ah3, bq.x, bq.y);
                mma16816(d[n][0], d[n][1], d[n][2], d[n][3],
                         ah0, ah1, ah2, ah3, bq.z, bq.w);
                mma16816(d[n][0], d[n][1], d[n][2], d[n][3],
                         al0, al1, al2, al3, bq.x, bq.y);
            }
        }
    }

    const int p0 = m0 + g;
    const int p1 = p0 + 8;
#pragma unroll
    for (int n = 0; n < 8; n++) {
        const int oc = n * 8 + 2 * tg;
        const float b0v = bias[oc];
        const float b1v = bias[oc + 1];
        long base0 = ((long)(b * CC + oc) * HH + h) * WW;
        long base1 = base0 + (long)HH * WW;
        float v00 = d[n][0] + b0v;
        float v01 = d[n][1] + b1v;
        float v10 = d[n][2] + b0v;
        float v11 = d[n][3] + b1v;
        if (add_res) {
            v00 += res[base0 + p0]; v01 += res[base1 + p0];
            v10 += res[base0 + p1]; v11 += res[base1 + p1];
        }
        outp[base0 + p0] = v00;
        outp[base1 + p0] = v01;
        outp[base0 + p1] = v10;
        outp[base1 + p1] = v11;
    }
}

// ---------------------------------------------------------------------------
// mean / eca / dw (R12 versions)
// ---------------------------------------------------------------------------
__global__ __launch_bounds__(256) void mean_kernel(const float* __restrict__ x0,
                                                   float* __restrict__ mean)
{
    const int bc = blockIdx.x;
    const float4* p4 = (const float4*)(x0 + (long)bc * NPIX);
    float s = 0.f;
    for (int i = threadIdx.x; i < NPIX / 4; i += 256) {
        float4 v = p4[i];
        s += v.x + v.y + v.z + v.w;
    }
    __shared__ float red[256];
    red[threadIdx.x] = s;
    __syncthreads();
    for (int off = 128; off > 0; off >>= 1) {
        if (threadIdx.x < off) red[threadIdx.x] += red[threadIdx.x + off];
        __syncthreads();
    }
    if (threadIdx.x == 0) mean[bc] = red[0] * (1.f / (float)NPIX);
}

__global__ void eca_kernel(const float* __restrict__ mean,
                           const float* __restrict__ w2,
                           const float* __restrict__ b2,
                           float* __restrict__ x2o)
{
    const int t = threadIdx.x;
    const int b = t >> 6, c = t & 63;
    float m0 = (c > 0)  ? mean[b * CC + c - 1] : 0.f;
    float m1 =            mean[b * CC + c];
    float m2 = (c < 63) ? mean[b * CC + c + 1] : 0.f;
    x2o[t] = w2[0] * m0 + w2[1] * m1 + w2[2] * m2 + b2[0];
}

__global__ __launch_bounds__(256) void dw_kernel(
    const float* __restrict__ x0, const float* __restrict__ w1,
    const float* __restrict__ b1, const float* __restrict__ x2,
    float* __restrict__ outp)
{
    __shared__ float t[10][130];
    const int h0 = blockIdx.x * 8;
    const int c  = blockIdx.y;
    const int b  = blockIdx.z;
    const float* src = x0 + (long)(b * CC + c) * NPIX;

    for (int i = threadIdx.x; i < 10 * 130; i += 256) {
        int r = i / 130, col = i % 130;
        int gh = h0 - 1 + r, gw = col - 1;
        float v = 0.f;
        if ((unsigned)gh < (unsigned)HH && (unsigned)gw < (unsigned)WW)
            v = src[gh * WW + gw];
        t[r][col] = v;
    }
    float wk[9];
#pragma unroll
    for (int k = 0; k < 9; k++) wk[k] = w1[c * 9 + k];
    const float bb = b1[c] + x2[b * CC + c];
    __syncthreads();

    float* dst = outp + (long)(b * CC + c) * NPIX + (long)h0 * WW;
    for (int p = threadIdx.x; p < 8 * WW; p += 256) {
        int r = p / WW, wc = p % WW;
        float a = bb;
#pragma unroll
        for (int dy = 0; dy < 3; dy++)
#pragma unroll
            for (int dx = 0; dx < 3; dx++)
                a += wk[dy * 3 + dx] * t[r + dy][wc + dx];
        dst[p] = a;
    }
}

// ---------------------------------------------------------------------------
// Dynamic conv via per-tap GEMMs (R12 structure); x0 halo staging rewritten:
// shift-only indexing + float4 central loads + constant-zero edges.
// ---------------------------------------------------------------------------
#define APITCH 72
#define DOFF_B3  50688
#define DYN_SMEM (50688 + 2304)

__global__ __launch_bounds__(256, 3) void dynconv_tap(
    const float* __restrict__ out1, const float* __restrict__ x0,
    const uint32_t* __restrict__ bp3, const float* __restrict__ b3,
    float* __restrict__ out2)
{
    extern __shared__ __align__(16) char smem[];
    __nv_bfloat16* Ahi = (__nv_bfloat16*)smem;           // [0, 18432)
    __nv_bfloat16* Alo = Ahi + 128 * APITCH;             // [18432, 36864)
    float* x0s = (float*)smem;                           // aliases A region
    float* b3s = (float*)(smem + DOFF_B3);

    const int tid  = threadIdx.x;
    const int warp = tid >> 5;
    const int lane = tid & 31;
    const int g    = lane >> 2;
    const int tg   = lane & 3;
    const int m0   = warp * 16;
    const int hrow = blockIdx.x;
    const int b = blockIdx.y;

    // ---- stage A: out1[b,:,h,:] -> [p][c] bf16 hi/lo (R12) -----------------
    {
        const long base = (long)b * CC * NPIX + (long)hrow * WW;
        for (int i = tid; i < 128 * 32; i += 256) {
            int p  = i >> 5;
            int cp = i & 31;
            float v0 = out1[base + (long)(2 * cp)     * NPIX + p];
            float v1 = out1[base + (long)(2 * cp + 1) * NPIX + p];
            __nv_bfloat16 bh0 = __float2bfloat16(v0);
            __nv_bfloat16 bh1 = __float2bfloat16(v1);
            __nv_bfloat16 bl0 = __float2bfloat16(v0 - __bfloat162float(bh0));
            __nv_bfloat16 bl1 = __float2bfloat16(v1 - __bfloat162float(bh1));
            __nv_bfloat162 ph(bh0, bh1), plp(bl0, bl1);
            *(uint32_t*)&Ahi[p * APITCH + 2 * cp] = *(uint32_t*)&ph;
            *(uint32_t*)&Alo[p * APITCH + 2 * cp] = *(uint32_t*)&plp;
        }
        for (int i = tid; i < 576; i += 256) b3s[i] = b3[i];
    }
    __syncthreads();

    // ---- A fragments in registers -----------------------------------------
    uint32_t Ah[4][4], Al[4][4];
#pragma unroll
    for (int k = 0; k < 4; k++) {
        int col = k * 16 + tg * 2;
        Ah[k][0] = *(const uint32_t*)&Ahi[(m0 + g)     * APITCH + col];
        Ah[k][1] = *(const uint32_t*)&Ahi[(m0 + g + 8) * APITCH + col];
        Ah[k][2] = *(const uint32_t*)&Ahi[(m0 + g)     * APITCH + col + 8];
        Ah[k][3] = *(const uint32_t*)&Ahi[(m0 + g + 8) * APITCH + col + 8];
        Al[k][0] = *(const uint32_t*)&Alo[(m0 + g)     * APITCH + col];
        Al[k][1] = *(const uint32_t*)&Alo[(m0 + g + 8) * APITCH + col];
        Al[k][2] = *(const uint32_t*)&Alo[(m0 + g)     * APITCH + col + 8];
        Al[k][3] = *(const uint32_t*)&Alo[(m0 + g + 8) * APITCH + col + 8];
    }

    const int p0 = m0 + g;
    const int p1 = p0 + 8;

    for (int hf = 0; hf < 2; hf++) {
        const int cbase = hf * 32;
        __syncthreads();   // fragments loaded / previous half done with x0s

        // ---- stage x0 halo [3][32][132] -- shift-only indexing ------------
        // edges j in {0,129,130,131} are always out-of-range -> zero
        for (int i = tid; i < 96 * 4; i += 256) {
            int row = i >> 2, e = i & 3;
            int j = (e == 0) ? 0 : (128 + e);
            x0s[row * 132 + j] = 0.f;
        }
        // central 128 columns via float4 (row = dy*32+c; all shifts/masks)
        for (int i = tid; i < 96 * 32; i += 256) {
            int row = i >> 5;
            int q   = i & 31;
            int dy  = row >> 5;
            int c   = row & 31;
            int gh  = hrow - 1 + dy;
            float4 v = make_float4(0.f, 0.f, 0.f, 0.f);
            if ((unsigned)gh < (unsigned)HH)
                v = *(const float4*)(x0 + ((long)(b * CC + cbase + c) * HH + gh) * WW + 4 * q);
            float* dstp = &x0s[row * 132 + 1 + 4 * q];
            dstp[0] = v.x; dstp[1] = v.y; dstp[2] = v.z; dstp[3] = v.w;
        }
        __syncthreads();

        float acc[4][4];
#pragma unroll
        for (int n = 0; n < 4; n++)
#pragma unroll
            for (int r = 0; r < 4; r++) acc[n][r] = 0.f;

#pragma unroll
        for (int k = 0; k < 9; k++) {
            const int dy = k / 3, dx = k - 3 * dy;
            const uint4* Bq = (const uint4*)bp3 + (size_t)(k * 2 + hf) * 512 + lane;
#pragma unroll
            for (int n = 0; n < 4; n++) {
                float d0 = 0.f, d1 = 0.f, d2 = 0.f, d3 = 0.f;
#pragma unroll
                for (int ks = 0; ks < 4; ks++) {
                    uint4 bq = Bq[(n * 4 + ks) * 32];
                    mma16816(d0, d1, d2, d3, Ah[ks][0], Ah[ks][1], Ah[ks][2], Ah[ks][3], bq.x, bq.y);
                    mma16816(d0, d1, d2, d3, Ah[ks][0], Ah[ks][1], Ah[ks][2], Ah[ks][3], bq.z, bq.w);
                    mma16816(d0, d1, d2, d3, Al[ks][0], Al[ks][1], Al[ks][2], Al[ks][3], bq.x, bq.y);
                }
                const int cl = n * 8 + 2 * tg;
                const float bb0 = b3s[(cbase + cl) * 9 + k];
                const float bb1 = b3s[(cbase + cl + 1) * 9 + k];
                const float* xr0 = &x0s[(dy * 32 + cl) * 132];
                const float* xr1 = xr0 + 132;
                acc[n][0] += (d0 + bb0) * xr0[p0 + dx];
                acc[n][1] += (d1 + bb1) * xr1[p0 + dx];
                acc[n][2] += (d2 + bb0) * xr0[p1 + dx];
                acc[n][3] += (d3 + bb1) * xr1[p1 + dx];
            }
        }

#pragma unroll
        for (int n = 0; n < 4; n++) {
            const int c = cbase + n * 8 + 2 * tg;
            long base0 = ((long)(b * CC + c) * HH + hrow) * WW;
            long base1 = base0 + (long)HH * WW;
            float v00 = acc[n][0], v01 = acc[n][1], v10 = acc[n][2], v11 = acc[n][3];
            v00 = (v00 >= 0.f) ? v00 : 0.2f * v00;
            v01 = (v01 >= 0.f) ? v01 : 0.2f * v01;
            v10 = (v10 >= 0.f) ? v10 : 0.2f * v10;
            v11 = (v11 >= 0.f) ? v11 : 0.2f * v11;
            out2[base0 + p0] = v00;
            out2[base1 + p0] = v01;
            out2[base0 + p1] = v10;
            out2[base1 + p1] = v11;
        }
    }
}

// ---------------------------------------------------------------------------
// Launch
// ---------------------------------------------------------------------------
extern "C" void kernel_launch(void* const* d_in, const int* in_sizes, int n_in,
                              void* d_out, int out_size)
{
    const float* x  = (const float*)d_in[0];
    const float* w0 = (const float*)d_in[1];
    const float* b0 = (const float*)d_in[2];
    const float* w1 = (const float*)d_in[3];
    const float* b1 = (const float*)d_in[4];
    const float* w2 = (const float*)d_in[5];
    const float* b2 = (const float*)d_in[6];
    const float* w3 = (const float*)d_in[7];
    const float* b3 = (const float*)d_in[8];
    const float* wf = (const float*)d_in[9];
    const float* bf = (const float*)d_in[10];
    float* out = (float*)d_out;

    float *px0, *pout1, *pout2, *pmean, *px2;
    uint32_t *pbpA, *pbpF, *pbp3;
    cudaGetSymbolAddress((void**)&px0,   g_x0);
    cudaGetSymbolAddress((void**)&pout1, g_out1);
    cudaGetSymbolAddress((void**)&pout2, g_out2);
    cudaGetSymbolAddress((void**)&pmean, g_mean);
    cudaGetSymbolAddress((void**)&px2,   g_x2);
    cudaGetSymbolAddress((void**)&pbpA,  g_bpA);
    cudaGetSymbolAddress((void**)&pbpF,  g_bpF);
    cudaGetSymbolAddress((void**)&pbp3,  g_bp3);

    cudaFuncSetAttribute(conv3x3_wmma,
                         cudaFuncAttributeMaxDynamicSharedMemorySize, CONV_SMEM);
    cudaFuncSetAttribute(dynconv_tap,
                         cudaFuncAttributeMaxDynamicSharedMemorySize, DYN_SMEM);

    // 0) weight permutations
    wconv_prep<<<(BPW_U32 + 255) / 256, 256>>>(w0, pbpA);
    wconv_prep<<<(BPW_U32 + 255) / 256, 256>>>(wf, pbpF);
    w3_prep_frag<<<(BP3_U32 + 255) / 256, 256>>>(w3, pbp3);
    // 1) conv0 on tensor cores
    conv3x3_wmma<<<dim3(HH, BN), 256, CONV_SMEM>>>(x, pbpA, b0, nullptr, px0, 0);
    // 2) per-channel spatial mean
    mean_kernel<<<BN * CC, 256>>>(px0, pmean);
    // 3) ECA conv1d over channel axis
    eca_kernel<<<1, BN * CC>>>(pmean, w2, b2, px2);
    // 4) depthwise + channel attention
    dw_kernel<<<dim3(HH / 8, CC, BN), 256>>>(px0, w1, b1, px2, pout1);
    // 5) dynamic conv: per-tap GEMMs, register-fused apply
    dynconv_tap<<<dim3(HH, BN), 256, DYN_SMEM>>>(pout1, px0, pbp3, b3, pout2);
    // 6) final conv on tensor cores + residual
    conv3x3_wmma<<<dim3(HH, BN), 256, CONV_SMEM>>>(pout2, pbpF, bf, x, out, 1);
}